// round 1
// baseline (speedup 1.0000x reference)
#include <cuda_runtime.h>
#include <math.h>

#define T_STEPS 512
#define BATCH   64
#define IN_F    512
#define HID     512
#define GATES   1024
#define SCAN_CTAS 128

// 128 MiB scratch for precomputed input gates gi[t][b][g]
__device__ float g_gi[(size_t)T_STEPS * BATCH * GATES];
__device__ unsigned int g_bar;

__global__ void init_kernel() {
    if (threadIdx.x == 0) g_bar = 0u;
}

// gi[m,g] = sum_k X[m,k] * Wih[g,k] + bih[g];  M=32768, N=1024, K=512
__global__ __launch_bounds__(256) void gi_gemm(const float* __restrict__ X,
                                               const float* __restrict__ W,
                                               const float* __restrict__ bih) {
    __shared__ float As[32][68];
    __shared__ float Bs[32][68];
    const int m0 = blockIdx.y * 64;
    const int n0 = blockIdx.x * 64;
    const int tid = threadIdx.x;
    const int tx = tid & 15, ty = tid >> 4;
    const int lk = tid & 31, lr = tid >> 5;
    float acc[4][4] = {};
    for (int k0 = 0; k0 < IN_F; k0 += 32) {
        __syncthreads();
        #pragma unroll
        for (int i = 0; i < 8; i++) {
            As[lk][lr + 8 * i] = X[(size_t)(m0 + lr + 8 * i) * IN_F + k0 + lk];
            Bs[lk][lr + 8 * i] = W[(size_t)(n0 + lr + 8 * i) * IN_F + k0 + lk];
        }
        __syncthreads();
        #pragma unroll
        for (int kk = 0; kk < 32; kk++) {
            const float4 a = *(const float4*)&As[kk][4 * ty];
            const float4 b = *(const float4*)&Bs[kk][4 * tx];
            acc[0][0] += a.x * b.x; acc[0][1] += a.x * b.y; acc[0][2] += a.x * b.z; acc[0][3] += a.x * b.w;
            acc[1][0] += a.y * b.x; acc[1][1] += a.y * b.y; acc[1][2] += a.y * b.z; acc[1][3] += a.y * b.w;
            acc[2][0] += a.z * b.x; acc[2][1] += a.z * b.y; acc[2][2] += a.z * b.z; acc[2][3] += a.z * b.w;
            acc[3][0] += a.w * b.x; acc[3][1] += a.w * b.y; acc[3][2] += a.w * b.z; acc[3][3] += a.w * b.w;
        }
    }
    const float4 bv = *(const float4*)&bih[n0 + 4 * tx];
    #pragma unroll
    for (int i = 0; i < 4; i++) {
        float4 v;
        v.x = acc[i][0] + bv.x;
        v.y = acc[i][1] + bv.y;
        v.z = acc[i][2] + bv.z;
        v.w = acc[i][3] + bv.w;
        *(float4*)&g_gi[(size_t)(m0 + 4 * ty + i) * GATES + n0 + 4 * tx] = v;
    }
}

// Persistent recurrent scan: 128 CTAs, each owns 4 hidden columns.
// h_t lives in out[t] (b-major), cross-step sync via software grid barrier.
__global__ __launch_bounds__(256) void scan_kernel(const float* __restrict__ Whh,
                                                   const float* __restrict__ bhh,
                                                   float* out) {
    __shared__ float Wf[4][512];
    __shared__ float Wn[4][512];
    __shared__ float hstage[64][4];
    const int tid = threadIdx.x;
    const int jl = tid >> 6;      // 0..3: hidden column within CTA
    const int b  = tid & 63;      // batch index
    const int j0 = blockIdx.x * 4;
    const int jg = j0 + jl;

    // Stage this CTA's W_hh rows (f-gate rows jg, n-gate rows 512+jg)
    for (int i = tid; i < 4 * 512; i += 256) {
        const int r = i >> 9, c = i & 511;
        Wf[r][c] = Whh[(size_t)(j0 + r) * HID + c];
        Wn[r][c] = Whh[(size_t)(HID + j0 + r) * HID + c];
    }
    const float bhf = bhh[jg];
    const float bhn = bhh[HID + jg];
    const unsigned G = gridDim.x;
    __syncthreads();

    for (int t = 0; t < T_STEPS; t++) {
        if (t > 0) {
            // grid barrier: all out[t-1] writes visible before anyone reads
            __threadfence();
            __syncthreads();
            if (tid == 0) {
                atomicAdd(&g_bar, 1u);
                const unsigned target = G * (unsigned)t;
                while (*((volatile unsigned*)&g_bar) < target) __nanosleep(64);
            }
            __syncthreads();
            __threadfence();
        }

        const float gif = g_gi[((size_t)t << 16) + ((size_t)b << 10) + jg];
        const float gin = g_gi[((size_t)t << 16) + ((size_t)b << 10) + HID + jg];

        float accf = 0.f, accn = 0.f;
        if (t > 0) {
            const float* hrow = out + ((size_t)(t - 1) * BATCH + b) * HID;
            float4 h[8];
            #pragma unroll
            for (int i = 0; i < 8; i++) h[i] = *(const float4*)(hrow + 4 * i);
            for (int kc = 0; kc < HID; kc += 32) {
                float4 hn[8];
                const int knext = (kc + 32) & (HID - 1);  // wraps to 0 on last iter (unused)
                #pragma unroll
                for (int i = 0; i < 8; i++) hn[i] = *(const float4*)(hrow + knext + 4 * i);
                #pragma unroll
                for (int i = 0; i < 8; i++) {
                    const float4 h4 = h[i];
                    const float4 wf = *(const float4*)(&Wf[jl][kc + 4 * i]);
                    const float4 wn = *(const float4*)(&Wn[jl][kc + 4 * i]);
                    accf += h4.x * wf.x; accn += h4.x * wn.x;
                    accf += h4.y * wf.y; accn += h4.y * wn.y;
                    accf += h4.z * wf.z; accn += h4.z * wn.z;
                    accf += h4.w * wf.w; accn += h4.w * wn.w;
                }
                #pragma unroll
                for (int i = 0; i < 8; i++) h[i] = hn[i];
            }
        }
        // t==0: h0 = 0 -> gh = bias_hh only
        const float f  = 1.f / (1.f + expf(-(gif + accf + bhf)));
        const float hv = tanhf(gin + f * (accn + bhn));

        // coalesce the out/h write through shared
        hstage[b][jl] = hv;
        __syncthreads();
        if (tid < 64) {
            const float4 v = *(const float4*)&hstage[tid][0];
            *(float4*)(out + ((size_t)t * BATCH + tid) * HID + j0) = v;
        }
        __syncthreads();
    }
}

extern "C" void kernel_launch(void* const* d_in, const int* in_sizes, int n_in,
                              void* d_out, int out_size) {
    const float* X   = (const float*)d_in[0];  // (512, 64, 512)
    const float* Wih = (const float*)d_in[1];  // (1024, 512)
    const float* Whh = (const float*)d_in[2];  // (1024, 512)
    const float* bih = (const float*)d_in[3];  // (1024,)
    const float* bhh = (const float*)d_in[4];  // (1024,)
    float* out = (float*)d_out;                // (512, 64, 512)

    init_kernel<<<1, 32>>>();
    dim3 g1(GATES / 64, (T_STEPS * BATCH) / 64);
    gi_gemm<<<g1, 256>>>(X, Wih, bih);
    scan_kernel<<<SCAN_CTAS, 256>>>(Whh, bhh, out);
}

// round 2
// speedup vs baseline: 1.6543x; 1.6543x over previous
#include <cuda_runtime.h>
#include <math.h>

#define T_STEPS 512
#define BATCH   64
#define IN_F    512
#define HID     512
#define GATES   1024
#define SCAN_CTAS 128
#define CHUNK   64
#define NCHUNK  (HID / CHUNK)   // 8
#define HPAD    68              // 64 + 4 pad -> conflict-free LDS/STS
#define WPAD    516             // 512 + 4 pad -> conflict-free W reads

// 128 MiB scratch for precomputed input gates gi[t][b][g]
__device__ float g_gi[(size_t)T_STEPS * BATCH * GATES];
__device__ unsigned int g_bar;

__global__ void init_kernel() {
    if (threadIdx.x == 0) g_bar = 0u;
}

// gi[m,g] = sum_k X[m,k] * Wih[g,k] + bih[g];  M=32768, N=1024, K=512
__global__ __launch_bounds__(256) void gi_gemm(const float* __restrict__ X,
                                               const float* __restrict__ W,
                                               const float* __restrict__ bih) {
    __shared__ float As[32][68];
    __shared__ float Bs[32][68];
    const int m0 = blockIdx.y * 64;
    const int n0 = blockIdx.x * 64;
    const int tid = threadIdx.x;
    const int tx = tid & 15, ty = tid >> 4;
    const int lk = tid & 31, lr = tid >> 5;
    float acc[4][4] = {};
    for (int k0 = 0; k0 < IN_F; k0 += 32) {
        __syncthreads();
        #pragma unroll
        for (int i = 0; i < 8; i++) {
            As[lk][lr + 8 * i] = X[(size_t)(m0 + lr + 8 * i) * IN_F + k0 + lk];
            Bs[lk][lr + 8 * i] = W[(size_t)(n0 + lr + 8 * i) * IN_F + k0 + lk];
        }
        __syncthreads();
        #pragma unroll
        for (int kk = 0; kk < 32; kk++) {
            const float4 a = *(const float4*)&As[kk][4 * ty];
            const float4 b = *(const float4*)&Bs[kk][4 * tx];
            acc[0][0] += a.x * b.x; acc[0][1] += a.x * b.y; acc[0][2] += a.x * b.z; acc[0][3] += a.x * b.w;
            acc[1][0] += a.y * b.x; acc[1][1] += a.y * b.y; acc[1][2] += a.y * b.z; acc[1][3] += a.y * b.w;
            acc[2][0] += a.z * b.x; acc[2][1] += a.z * b.y; acc[2][2] += a.z * b.z; acc[2][3] += a.z * b.w;
            acc[3][0] += a.w * b.x; acc[3][1] += a.w * b.y; acc[3][2] += a.w * b.z; acc[3][3] += a.w * b.w;
        }
    }
    const float4 bv = *(const float4*)&bih[n0 + 4 * tx];
    #pragma unroll
    for (int i = 0; i < 4; i++) {
        float4 v;
        v.x = acc[i][0] + bv.x;
        v.y = acc[i][1] + bv.y;
        v.z = acc[i][2] + bv.z;
        v.w = acc[i][3] + bv.w;
        *(float4*)&g_gi[(size_t)(m0 + 4 * ty + i) * GATES + n0 + 4 * tx] = v;
    }
}

// Persistent recurrent scan: 128 CTAs, each owns 4 hidden columns.
// Thread map: jl = tid&3 (j within CTA), b = tid>>2. A warp spans 8 b x 4 j,
// so h shared-loads are 8 distinct float4 (conflict-free with pad), W loads
// are 4-way broadcast, gi/out global accesses hit 8 sectors per warp.
// h rows are staged coalesced into double-buffered 64-k smem chunks.
__global__ __launch_bounds__(256) void scan_kernel(const float* __restrict__ Whh,
                                                   const float* __restrict__ bhh,
                                                   float* __restrict__ out) {
    __shared__ float Wf[4][WPAD];
    __shared__ float Wn[4][WPAD];
    __shared__ float hsm[2][BATCH * HPAD];

    const int tid = threadIdx.x;
    const int jl  = tid & 3;
    const int b   = tid >> 2;
    const int j0  = blockIdx.x * 4;
    const int jg  = j0 + jl;

    // staging map: each thread loads 4 float4 (4 b-rows, one quad each)
    const int sb  = tid >> 4;   // 0..15 base b row
    const int skq = tid & 15;   // 0..15 float4 within 64-float chunk row

    // Stage this CTA's W_hh rows (f-gate rows jg, n-gate rows 512+jg)
    for (int i = tid; i < 4 * 512; i += 256) {
        const int r = i >> 9, c = i & 511;
        Wf[r][c] = Whh[(size_t)(j0 + r) * HID + c];
        Wn[r][c] = Whh[(size_t)(HID + j0 + r) * HID + c];
    }
    const float bhf = bhh[jg];
    const float bhn = bhh[HID + jg];
    __syncthreads();

    for (int t = 0; t < T_STEPS; t++) {
        if (t > 0) {
            // grid barrier: all out[t-1] writes visible before anyone reads
            __threadfence();
            __syncthreads();
            if (tid == 0) atomicAdd(&g_bar, 1u);   // return unused -> REDG
            const unsigned target = (unsigned)SCAN_CTAS * (unsigned)t;
            while (*((volatile unsigned*)&g_bar) < target) __nanosleep(32);
            __threadfence();
        }

        const float gif = g_gi[((size_t)t << 16) + ((size_t)b << 10) + jg];
        const float gin = g_gi[((size_t)t << 16) + ((size_t)b << 10) + HID + jg];

        float accf = 0.f, accn = 0.f;
        if (t > 0) {
            const float* hbase = out + (size_t)(t - 1) * BATCH * HID;

            // prologue: stage chunk 0
            float4 r[4];
            #pragma unroll
            for (int i = 0; i < 4; i++)
                r[i] = *(const float4*)(hbase + (size_t)(sb + 16 * i) * HID + 4 * skq);
            #pragma unroll
            for (int i = 0; i < 4; i++)
                *(float4*)&hsm[0][(sb + 16 * i) * HPAD + 4 * skq] = r[i];
            __syncthreads();

            #pragma unroll
            for (int c = 0; c < NCHUNK; c++) {
                if (c + 1 < NCHUNK) {
                    #pragma unroll
                    for (int i = 0; i < 4; i++)
                        r[i] = *(const float4*)(hbase + (size_t)(sb + 16 * i) * HID
                                                + (c + 1) * CHUNK + 4 * skq);
                }
                const float* hb  = &hsm[c & 1][b * HPAD];
                const float* wfp = &Wf[jl][c * CHUNK];
                const float* wnp = &Wn[jl][c * CHUNK];
                #pragma unroll
                for (int q = 0; q < 16; q++) {
                    const float4 h4  = *(const float4*)(hb + 4 * q);
                    const float4 wf4 = *(const float4*)(wfp + 4 * q);
                    const float4 wn4 = *(const float4*)(wnp + 4 * q);
                    accf += h4.x * wf4.x; accn += h4.x * wn4.x;
                    accf += h4.y * wf4.y; accn += h4.y * wn4.y;
                    accf += h4.z * wf4.z; accn += h4.z * wn4.z;
                    accf += h4.w * wf4.w; accn += h4.w * wn4.w;
                }
                if (c + 1 < NCHUNK) {
                    #pragma unroll
                    for (int i = 0; i < 4; i++)
                        *(float4*)&hsm[(c + 1) & 1][(sb + 16 * i) * HPAD + 4 * skq] = r[i];
                    __syncthreads();
                }
            }
        }
        // t==0: h0 = 0 -> gh = bias_hh only
        const float f  = 1.f / (1.f + expf(-(gif + accf + bhf)));
        const float hv = tanhf(gin + f * (accn + bhn));

        out[((size_t)t * BATCH + b) * HID + jg] = hv;
    }
}

extern "C" void kernel_launch(void* const* d_in, const int* in_sizes, int n_in,
                              void* d_out, int out_size) {
    const float* X   = (const float*)d_in[0];  // (512, 64, 512)
    const float* Wih = (const float*)d_in[1];  // (1024, 512)
    const float* Whh = (const float*)d_in[2];  // (1024, 512)
    const float* bih = (const float*)d_in[3];  // (1024,)
    const float* bhh = (const float*)d_in[4];  // (1024,)
    float* out = (float*)d_out;                // (512, 64, 512)

    init_kernel<<<1, 32>>>();
    dim3 g1(GATES / 64, (T_STEPS * BATCH) / 64);
    gi_gemm<<<g1, 256>>>(X, Wih, bih);
    scan_kernel<<<SCAN_CTAS, 256>>>(Whh, bhh, out);
}

// round 3
// speedup vs baseline: 2.1078x; 1.2741x over previous
#include <cuda_runtime.h>
#include <math.h>

#define T_STEPS 512
#define BATCH   64
#define IN_F    512
#define HID     512
#define GATES   1024
#define SCAN_CTAS 128
#define CHUNK   64
#define NCHUNK  (HID / CHUNK)   // 8
#define HPAD    68              // 64 + 4 pad -> conflict-free LDS/STS
#define WPAD    516             // 512 + 4 pad -> conflict-free W reads

// 128 MiB scratch for precomputed input gates gi[t][b][g]
__device__ float g_gi[(size_t)T_STEPS * BATCH * GATES];
__device__ unsigned int g_bar;   // zero at load; self-reset by last CTA each run

__device__ __forceinline__ unsigned ld_acquire_gpu(const unsigned* p) {
    unsigned v;
    asm volatile("ld.acquire.gpu.global.u32 %0, [%1];" : "=r"(v) : "l"(p));
    return v;
}
__device__ __forceinline__ void red_release_gpu_add1(unsigned* p) {
    asm volatile("red.release.gpu.global.add.u32 [%0], 1;" :: "l"(p) : "memory");
}

// gi[m,g] = sum_k X[m,k] * Wih[g,k] + bih[g];  M=32768, N=1024, K=512
__global__ __launch_bounds__(256) void gi_gemm(const float* __restrict__ X,
                                               const float* __restrict__ W,
                                               const float* __restrict__ bih) {
    __shared__ float As[32][68];
    __shared__ float Bs[32][68];
    const int m0 = blockIdx.y * 64;
    const int n0 = blockIdx.x * 64;
    const int tid = threadIdx.x;
    const int tx = tid & 15, ty = tid >> 4;
    const int lk = tid & 31, lr = tid >> 5;
    float acc[4][4] = {};
    for (int k0 = 0; k0 < IN_F; k0 += 32) {
        __syncthreads();
        #pragma unroll
        for (int i = 0; i < 8; i++) {
            As[lk][lr + 8 * i] = X[(size_t)(m0 + lr + 8 * i) * IN_F + k0 + lk];
            Bs[lk][lr + 8 * i] = W[(size_t)(n0 + lr + 8 * i) * IN_F + k0 + lk];
        }
        __syncthreads();
        #pragma unroll
        for (int kk = 0; kk < 32; kk++) {
            const float4 a = *(const float4*)&As[kk][4 * ty];
            const float4 b = *(const float4*)&Bs[kk][4 * tx];
            acc[0][0] += a.x * b.x; acc[0][1] += a.x * b.y; acc[0][2] += a.x * b.z; acc[0][3] += a.x * b.w;
            acc[1][0] += a.y * b.x; acc[1][1] += a.y * b.y; acc[1][2] += a.y * b.z; acc[1][3] += a.y * b.w;
            acc[2][0] += a.z * b.x; acc[2][1] += a.z * b.y; acc[2][2] += a.z * b.z; acc[2][3] += a.z * b.w;
            acc[3][0] += a.w * b.x; acc[3][1] += a.w * b.y; acc[3][2] += a.w * b.z; acc[3][3] += a.w * b.w;
        }
    }
    const float4 bv = *(const float4*)&bih[n0 + 4 * tx];
    #pragma unroll
    for (int i = 0; i < 4; i++) {
        float4 v;
        v.x = acc[i][0] + bv.x;
        v.y = acc[i][1] + bv.y;
        v.z = acc[i][2] + bv.z;
        v.w = acc[i][3] + bv.w;
        *(float4*)&g_gi[(size_t)(m0 + 4 * ty + i) * GATES + n0 + 4 * tx] = v;
    }
}

// Persistent recurrent scan: 128 CTAs x 256 threads, each CTA owns 4 hidden
// columns. Thread map: jl = tid&3, b = tid>>2. Grid barrier: single arriver/
// poller per CTA with release/acquire semantics; barrier self-resets at end.
__global__ __launch_bounds__(256) void scan_kernel(const float* __restrict__ Whh,
                                                   const float* __restrict__ bhh,
                                                   float* __restrict__ out) {
    __shared__ float Wf[4][WPAD];
    __shared__ float Wn[4][WPAD];
    __shared__ float hsm[2][BATCH * HPAD];

    const int tid = threadIdx.x;
    const int jl  = tid & 3;
    const int b   = tid >> 2;
    const int j0  = blockIdx.x * 4;
    const int jg  = j0 + jl;

    // staging map: each thread loads 4 float4 (4 b-rows, one quad each)
    const int sb  = tid >> 4;   // 0..15 base b row
    const int skq = tid & 15;   // 0..15 float4 within 64-float chunk row

    // Stage this CTA's W_hh rows (f-gate rows jg, n-gate rows 512+jg)
    for (int i = tid; i < 4 * 512; i += 256) {
        const int r = i >> 9, c = i & 511;
        Wf[r][c] = Whh[(size_t)(j0 + r) * HID + c];
        Wn[r][c] = Whh[(size_t)(HID + j0 + r) * HID + c];
    }
    const float bhf = bhh[jg];
    const float bhn = bhh[HID + jg];
    __syncthreads();

    // prefetch gi for t=0
    float gif = g_gi[((size_t)b << 10) + jg];
    float gin = g_gi[((size_t)b << 10) + HID + jg];

    for (int t = 0; t < T_STEPS; t++) {
        if (t > 0) {
            // grid barrier: 1 arriver + 1 poller per CTA, acq/rel ordering
            __syncthreads();
            if (tid == 0) {
                red_release_gpu_add1(&g_bar);
                const unsigned target = (unsigned)SCAN_CTAS * (unsigned)t;
                while (ld_acquire_gpu(&g_bar) < target) __nanosleep(64);
            }
            __syncthreads();
        }

        // prefetch gi for next step (h-independent, hides DRAM latency)
        const int tn = (t + 1 < T_STEPS) ? (t + 1) : t;
        const float gif_n = g_gi[((size_t)tn << 16) + ((size_t)b << 10) + jg];
        const float gin_n = g_gi[((size_t)tn << 16) + ((size_t)b << 10) + HID + jg];

        float accf0 = 0.f, accf1 = 0.f, accn0 = 0.f, accn1 = 0.f;
        if (t > 0) {
            const float* hbase = out + (size_t)(t - 1) * BATCH * HID;

            // prologue: stage chunk 0
            float4 r[4];
            #pragma unroll
            for (int i = 0; i < 4; i++)
                r[i] = *(const float4*)(hbase + (size_t)(sb + 16 * i) * HID + 4 * skq);
            #pragma unroll
            for (int i = 0; i < 4; i++)
                *(float4*)&hsm[0][(sb + 16 * i) * HPAD + 4 * skq] = r[i];
            __syncthreads();

            #pragma unroll
            for (int c = 0; c < NCHUNK; c++) {
                if (c + 1 < NCHUNK) {
                    #pragma unroll
                    for (int i = 0; i < 4; i++)
                        r[i] = *(const float4*)(hbase + (size_t)(sb + 16 * i) * HID
                                                + (c + 1) * CHUNK + 4 * skq);
                }
                const float* hb  = &hsm[c & 1][b * HPAD];
                const float* wfp = &Wf[jl][c * CHUNK];
                const float* wnp = &Wn[jl][c * CHUNK];
                #pragma unroll
                for (int q = 0; q < 16; q++) {
                    const float4 h4  = *(const float4*)(hb + 4 * q);
                    const float4 wf4 = *(const float4*)(wfp + 4 * q);
                    const float4 wn4 = *(const float4*)(wnp + 4 * q);
                    accf0 += h4.x * wf4.x; accn0 += h4.x * wn4.x;
                    accf1 += h4.y * wf4.y; accn1 += h4.y * wn4.y;
                    accf0 += h4.z * wf4.z; accn0 += h4.z * wn4.z;
                    accf1 += h4.w * wf4.w; accn1 += h4.w * wn4.w;
                }
                if (c + 1 < NCHUNK) {
                    #pragma unroll
                    for (int i = 0; i < 4; i++)
                        *(float4*)&hsm[(c + 1) & 1][(sb + 16 * i) * HPAD + 4 * skq] = r[i];
                    __syncthreads();
                }
            }
        }
        // t==0: h0 = 0 -> gh = bias_hh only
        const float accf = accf0 + accf1;
        const float accn = accn0 + accn1;
        const float f  = 1.f / (1.f + expf(-(gif + accf + bhf)));
        const float hv = tanhf(gin + f * (accn + bhn));

        out[((size_t)t * BATCH + b) * HID + jg] = hv;

        gif = gif_n;
        gin = gin_n;
    }

    // self-reset barrier for next graph replay: last arriving CTA (which can
    // only arrive after every CTA has passed every wait) clears the counter.
    __syncthreads();
    if (tid == 0) {
        const unsigned r = atomicAdd(&g_bar, 1u);
        if (r == (unsigned)SCAN_CTAS * (unsigned)T_STEPS - 1u)
            *((volatile unsigned*)&g_bar) = 0u;
    }
}

extern "C" void kernel_launch(void* const* d_in, const int* in_sizes, int n_in,
                              void* d_out, int out_size) {
    const float* X   = (const float*)d_in[0];  // (512, 64, 512)
    const float* Wih = (const float*)d_in[1];  // (1024, 512)
    const float* Whh = (const float*)d_in[2];  // (1024, 512)
    const float* bih = (const float*)d_in[3];  // (1024,)
    const float* bhh = (const float*)d_in[4];  // (1024,)
    float* out = (float*)d_out;                // (512, 64, 512)

    dim3 g1(GATES / 64, (T_STEPS * BATCH) / 64);
    gi_gemm<<<g1, 256>>>(X, Wih, bih);
    scan_kernel<<<SCAN_CTAS, 256>>>(Whh, bhh, out);
}

// round 4
// speedup vs baseline: 2.1538x; 1.0218x over previous
#include <cuda_runtime.h>
#include <math.h>

#define T_STEPS 512
#define BATCH   64
#define IN_F    512
#define HID     512
#define GATES   1024
#define SCAN_CTAS 128

#define WPADF   516                    // 512 + 4 floats pad (W rows)
#define HSTRIDE 129                    // h row stride in float4 (=516 floats)
// dynamic smem: Wf[4][516] | Wn[4][516] | h[64][129 float4]
#define SMEM_W_FLOATS (8 * WPADF)
#define SMEM_BYTES (SMEM_W_FLOATS * 4 + BATCH * HSTRIDE * 16)

// 128 MiB scratch for precomputed input gates gi[t][b][g]
__device__ float g_gi[(size_t)T_STEPS * BATCH * GATES];
__device__ unsigned int g_bar;   // zero at load; self-reset by last CTA each run

__device__ __forceinline__ unsigned ld_acquire_gpu(const unsigned* p) {
    unsigned v;
    asm volatile("ld.acquire.gpu.global.u32 %0, [%1];" : "=r"(v) : "l"(p));
    return v;
}
__device__ __forceinline__ void red_release_gpu_add1(unsigned* p) {
    asm volatile("red.release.gpu.global.add.u32 [%0], 1;" :: "l"(p) : "memory");
}

// gi[m,g] = sum_k X[m,k] * Wih[g,k] + bih[g];  M=32768, N=1024, K=512
__global__ __launch_bounds__(256) void gi_gemm(const float* __restrict__ X,
                                               const float* __restrict__ W,
                                               const float* __restrict__ bih) {
    __shared__ float As[32][68];
    __shared__ float Bs[32][68];
    const int m0 = blockIdx.y * 64;
    const int n0 = blockIdx.x * 64;
    const int tid = threadIdx.x;
    const int tx = tid & 15, ty = tid >> 4;
    const int lk = tid & 31, lr = tid >> 5;
    float acc[4][4] = {};
    for (int k0 = 0; k0 < IN_F; k0 += 32) {
        __syncthreads();
        #pragma unroll
        for (int i = 0; i < 8; i++) {
            As[lk][lr + 8 * i] = X[(size_t)(m0 + lr + 8 * i) * IN_F + k0 + lk];
            Bs[lk][lr + 8 * i] = W[(size_t)(n0 + lr + 8 * i) * IN_F + k0 + lk];
        }
        __syncthreads();
        #pragma unroll
        for (int kk = 0; kk < 32; kk++) {
            const float4 a = *(const float4*)&As[kk][4 * ty];
            const float4 b = *(const float4*)&Bs[kk][4 * tx];
            acc[0][0] += a.x * b.x; acc[0][1] += a.x * b.y; acc[0][2] += a.x * b.z; acc[0][3] += a.x * b.w;
            acc[1][0] += a.y * b.x; acc[1][1] += a.y * b.y; acc[1][2] += a.y * b.z; acc[1][3] += a.y * b.w;
            acc[2][0] += a.z * b.x; acc[2][1] += a.z * b.y; acc[2][2] += a.z * b.z; acc[2][3] += a.z * b.w;
            acc[3][0] += a.w * b.x; acc[3][1] += a.w * b.y; acc[3][2] += a.w * b.z; acc[3][3] += a.w * b.w;
        }
    }
    const float4 bv = *(const float4*)&bih[n0 + 4 * tx];
    #pragma unroll
    for (int i = 0; i < 4; i++) {
        float4 v;
        v.x = acc[i][0] + bv.x;
        v.y = acc[i][1] + bv.y;
        v.z = acc[i][2] + bv.z;
        v.w = acc[i][3] + bv.w;
        *(float4*)&g_gi[(size_t)(m0 + 4 * ty + i) * GATES + n0 + 4 * tx] = v;
    }
}

// Persistent recurrent scan: 128 CTAs x 256 threads, each CTA owns 4 hidden
// columns. Full h tile (64x512) resident in dynamic smem; staged per step in
// 4 software-pipelined quarters (LDG q+1 -> compute q -> STS q+1 -> sync).
__global__ __launch_bounds__(256) void scan_kernel(const float* __restrict__ Whh,
                                                   const float* __restrict__ bhh,
                                                   float* __restrict__ out) {
    extern __shared__ float sm[];
    float*  Wf  = sm;                       // [4][516]
    float*  Wn  = sm + 4 * WPADF;           // [4][516]
    float4* hsm = (float4*)(sm + SMEM_W_FLOATS);  // [64][129]

    const int tid = threadIdx.x;
    const int jl  = tid & 3;
    const int b   = tid >> 2;
    const int j0  = blockIdx.x * 4;
    const int jg  = j0 + jl;

    // staging map: quarter = 128 k-floats (32 float4) x 64 rows = 2048 float4;
    // thread handles f = tid + 256*i, i<8: row = f>>5, f4-col-in-quarter = f&31.
    const float* wfp = Wf + jl * WPADF;
    const float* wnp = Wn + jl * WPADF;
    const float4* hb = hsm + b * HSTRIDE;

    // Stage this CTA's W_hh rows (f-gate rows jg, n-gate rows 512+jg)
    for (int i = tid; i < 4 * 512; i += 256) {
        const int r = i >> 9, c = i & 511;
        Wf[r * WPADF + c] = Whh[(size_t)(j0 + r) * HID + c];
        Wn[r * WPADF + c] = Whh[(size_t)(HID + j0 + r) * HID + c];
    }
    const float bhf = bhh[jg];
    const float bhn = bhh[HID + jg];
    __syncthreads();

    // prefetch gi for t=0
    float gif = g_gi[((size_t)b << 10) + jg];
    float gin = g_gi[((size_t)b << 10) + HID + jg];

    for (int t = 0; t < T_STEPS; t++) {
        if (t > 0) {
            // grid barrier: 1 arriver + 1 poller per CTA, acq/rel ordering
            __syncthreads();
            if (tid == 0) {
                red_release_gpu_add1(&g_bar);
                const unsigned target = (unsigned)SCAN_CTAS * (unsigned)t;
                while (ld_acquire_gpu(&g_bar) < target) __nanosleep(32);
            }
            __syncthreads();
        }

        // prefetch gi for next step (h-independent, hides DRAM latency)
        const int tn = (t + 1 < T_STEPS) ? (t + 1) : t;
        const float gif_n = g_gi[((size_t)tn << 16) + ((size_t)b << 10) + jg];
        const float gin_n = g_gi[((size_t)tn << 16) + ((size_t)b << 10) + HID + jg];

        float accf0 = 0.f, accf1 = 0.f, accn0 = 0.f, accn1 = 0.f;
        if (t > 0) {
            const float* hbase = out + (size_t)(t - 1) * BATCH * HID;

            // prologue: stage quarter 0
            float4 r[8];
            #pragma unroll
            for (int i = 0; i < 8; i++) {
                const int f = tid + 256 * i;
                r[i] = *(const float4*)(hbase + (f >> 5) * HID + 4 * (f & 31));
            }
            #pragma unroll
            for (int i = 0; i < 8; i++) {
                const int f = tid + 256 * i;
                hsm[(f >> 5) * HSTRIDE + (f & 31)] = r[i];
            }
            __syncthreads();

            #pragma unroll
            for (int qt = 0; qt < 4; qt++) {
                float4 r2[8];
                if (qt < 3) {
                    #pragma unroll
                    for (int i = 0; i < 8; i++) {
                        const int f = tid + 256 * i;
                        r2[i] = *(const float4*)(hbase + (f >> 5) * HID
                                                 + (qt + 1) * 128 + 4 * (f & 31));
                    }
                }
                const float4* hq = hb + qt * 32;
                const float*  wfq = wfp + qt * 128;
                const float*  wnq = wnp + qt * 128;
                #pragma unroll
                for (int q = 0; q < 32; q++) {
                    const float4 h4  = hq[q];
                    const float4 wf4 = *(const float4*)(wfq + 4 * q);
                    const float4 wn4 = *(const float4*)(wnq + 4 * q);
                    accf0 += h4.x * wf4.x; accn0 += h4.x * wn4.x;
                    accf1 += h4.y * wf4.y; accn1 += h4.y * wn4.y;
                    accf0 += h4.z * wf4.z; accn0 += h4.z * wn4.z;
                    accf1 += h4.w * wf4.w; accn1 += h4.w * wn4.w;
                }
                if (qt < 3) {
                    #pragma unroll
                    for (int i = 0; i < 8; i++) {
                        const int f = tid + 256 * i;
                        hsm[(f >> 5) * HSTRIDE + (qt + 1) * 32 + (f & 31)] = r2[i];
                    }
                    __syncthreads();
                }
            }
        }
        // t==0: h0 = 0 -> gh = bias_hh only
        const float accf = accf0 + accf1;
        const float accn = accn0 + accn1;
        const float f  = 1.f / (1.f + expf(-(gif + accf + bhf)));
        const float hv = tanhf(gin + f * (accn + bhn));

        out[((size_t)t * BATCH + b) * HID + jg] = hv;

        gif = gif_n;
        gin = gin_n;
    }

    // self-reset barrier for next graph replay: last arriving CTA (which can
    // only arrive after every CTA has passed every wait) clears the counter.
    __syncthreads();
    if (tid == 0) {
        const unsigned r = atomicAdd(&g_bar, 1u);
        if (r == (unsigned)SCAN_CTAS * (unsigned)T_STEPS - 1u)
            *((volatile unsigned*)&g_bar) = 0u;
    }
}

extern "C" void kernel_launch(void* const* d_in, const int* in_sizes, int n_in,
                              void* d_out, int out_size) {
    const float* X   = (const float*)d_in[0];  // (512, 64, 512)
    const float* Wih = (const float*)d_in[1];  // (1024, 512)
    const float* Whh = (const float*)d_in[2];  // (1024, 512)
    const float* bih = (const float*)d_in[3];  // (1024,)
    const float* bhh = (const float*)d_in[4];  // (1024,)
    float* out = (float*)d_out;                // (512, 64, 512)

    cudaFuncSetAttribute(scan_kernel,
                         cudaFuncAttributeMaxDynamicSharedMemorySize, SMEM_BYTES);

    dim3 g1(GATES / 64, (T_STEPS * BATCH) / 64);
    gi_gemm<<<g1, 256>>>(X, Wih, bih);
    scan_kernel<<<SCAN_CTAS, 256, SMEM_BYTES>>>(Whh, bhh, out);
}

// round 5
// speedup vs baseline: 2.3053x; 1.0704x over previous
#include <cuda_runtime.h>
#include <math.h>

#define T_STEPS 512
#define BATCH   64
#define IN_F    512
#define HID     512
#define GATES   1024
#define SCAN_CTAS 128
#define SCAN_THREADS 512

#define WPADF   516                    // 512 + 4 floats pad (W rows, 16B-aligned stride)
#define HSTRIDE 129                    // h row stride in float4 (=516 floats)
#define SMEM_W_FLOATS (8 * WPADF)
#define SMEM_H_FLOAT4 (BATCH * HSTRIDE)
#define SMEM_RED_FLOATS (BATCH * 4 * 2)
#define SMEM_BYTES (SMEM_W_FLOATS * 4 + SMEM_H_FLOAT4 * 16 + SMEM_RED_FLOATS * 4)

// 128 MiB scratch for precomputed input gates gi[t][b][g]
__device__ float g_gi[(size_t)T_STEPS * BATCH * GATES];
__device__ unsigned int g_bar;   // zero at load; self-reset by last CTA each run

__device__ __forceinline__ unsigned ld_acquire_gpu(const unsigned* p) {
    unsigned v;
    asm volatile("ld.acquire.gpu.global.u32 %0, [%1];" : "=r"(v) : "l"(p));
    return v;
}
__device__ __forceinline__ void red_release_gpu_add1(unsigned* p) {
    asm volatile("red.release.gpu.global.add.u32 [%0], 1;" :: "l"(p) : "memory");
}
// packed fp32 FMA: acc.{lo,hi} += a.{lo,hi} * b.{lo,hi}  (exact fp32, 2 lanes/inst)
__device__ __forceinline__ void fma2(unsigned long long& acc,
                                     unsigned long long a, unsigned long long b) {
    asm("fma.rn.f32x2 %0, %1, %2, %0;" : "+l"(acc) : "l"(a), "l"(b));
}
__device__ __forceinline__ float hsum2(unsigned long long v) {
    float lo, hi;
    asm("mov.b64 {%0, %1}, %2;" : "=f"(lo), "=f"(hi) : "l"(v));
    return lo + hi;
}

// gi[m,g] = sum_k X[m,k] * Wih[g,k] + bih[g];  M=32768, N=1024, K=512
__global__ __launch_bounds__(256) void gi_gemm(const float* __restrict__ X,
                                               const float* __restrict__ W,
                                               const float* __restrict__ bih) {
    __shared__ float As[32][68];
    __shared__ float Bs[32][68];
    const int m0 = blockIdx.y * 64;
    const int n0 = blockIdx.x * 64;
    const int tid = threadIdx.x;
    const int tx = tid & 15, ty = tid >> 4;
    const int lk = tid & 31, lr = tid >> 5;
    float acc[4][4] = {};
    for (int k0 = 0; k0 < IN_F; k0 += 32) {
        __syncthreads();
        #pragma unroll
        for (int i = 0; i < 8; i++) {
            As[lk][lr + 8 * i] = X[(size_t)(m0 + lr + 8 * i) * IN_F + k0 + lk];
            Bs[lk][lr + 8 * i] = W[(size_t)(n0 + lr + 8 * i) * IN_F + k0 + lk];
        }
        __syncthreads();
        #pragma unroll
        for (int kk = 0; kk < 32; kk++) {
            const float4 a = *(const float4*)&As[kk][4 * ty];
            const float4 b = *(const float4*)&Bs[kk][4 * tx];
            acc[0][0] += a.x * b.x; acc[0][1] += a.x * b.y; acc[0][2] += a.x * b.z; acc[0][3] += a.x * b.w;
            acc[1][0] += a.y * b.x; acc[1][1] += a.y * b.y; acc[1][2] += a.y * b.z; acc[1][3] += a.y * b.w;
            acc[2][0] += a.z * b.x; acc[2][1] += a.z * b.y; acc[2][2] += a.z * b.z; acc[2][3] += a.z * b.w;
            acc[3][0] += a.w * b.x; acc[3][1] += a.w * b.y; acc[3][2] += a.w * b.z; acc[3][3] += a.w * b.w;
        }
    }
    const float4 bv = *(const float4*)&bih[n0 + 4 * tx];
    #pragma unroll
    for (int i = 0; i < 4; i++) {
        float4 v;
        v.x = acc[i][0] + bv.x;
        v.y = acc[i][1] + bv.y;
        v.z = acc[i][2] + bv.z;
        v.w = acc[i][3] + bv.w;
        *(float4*)&g_gi[(size_t)(m0 + 4 * ty + i) * GATES + n0 + 4 * tx] = v;
    }
}

// Persistent recurrent scan: 128 CTAs x 512 threads. Each CTA owns 4 hidden
// columns; threads split K in half (half = tid>>8) and reduce via smem.
// Inner product uses packed fma.rn.f32x2 (2 k-lanes per instruction).
__global__ __launch_bounds__(SCAN_THREADS) void scan_kernel(const float* __restrict__ Whh,
                                                            const float* __restrict__ bhh,
                                                            float* __restrict__ out) {
    extern __shared__ float sm[];
    float*  Wf   = sm;                                   // [4][516]
    float*  Wn   = sm + 4 * WPADF;                       // [4][516]
    float4* hsm  = (float4*)(sm + SMEM_W_FLOATS);        // [64][129]
    float2* hred = (float2*)(sm + SMEM_W_FLOATS + SMEM_H_FLOAT4 * 4); // [64*4]

    const int tid  = threadIdx.x;
    const int jl   = tid & 3;
    const int b    = (tid >> 2) & 63;
    const int half = tid >> 8;            // 0 or 1: which 256-k slab
    const int j0   = blockIdx.x * 4;
    const int jg   = j0 + jl;

    // per-thread compute pointers (float4 / ulonglong2 views)
    const float4* hb  = hsm + b * HSTRIDE + half * 64;          // 64 float4 = 256 k
    const float4* wfq = (const float4*)(Wf + jl * WPADF) + half * 64;
    const float4* wnq = (const float4*)(Wn + jl * WPADF) + half * 64;

    // Stage this CTA's W_hh rows (f-gate rows jg, n-gate rows 512+jg)
    for (int i = tid; i < 4 * 512; i += SCAN_THREADS) {
        const int r = i >> 9, c = i & 511;
        Wf[r * WPADF + c] = Whh[(size_t)(j0 + r) * HID + c];
        Wn[r * WPADF + c] = Whh[(size_t)(HID + j0 + r) * HID + c];
    }
    const float bhf = bhh[jg];
    const float bhn = bhh[HID + jg];
    __syncthreads();

    // gi prefetch (gates are evaluated by half==0 threads only)
    float gif = 0.f, gin = 0.f;
    if (half == 0) {
        gif = g_gi[((size_t)b << 10) + jg];
        gin = g_gi[((size_t)b << 10) + HID + jg];
    }

    for (int t = 0; t < T_STEPS; t++) {
        if (t > 0) {
            // grid barrier: 1 arriver + 1 poller per CTA, acq/rel ordering
            __syncthreads();
            if (tid == 0) {
                red_release_gpu_add1(&g_bar);
                const unsigned target = (unsigned)SCAN_CTAS * (unsigned)t;
                while (ld_acquire_gpu(&g_bar) < target) __nanosleep(32);
            }
            __syncthreads();
        }

        // prefetch next step's gi (h-independent)
        float gif_n = 0.f, gin_n = 0.f;
        if (half == 0) {
            const int tn = (t + 1 < T_STEPS) ? (t + 1) : t;
            gif_n = g_gi[((size_t)tn << 16) + ((size_t)b << 10) + jg];
            gin_n = g_gi[((size_t)tn << 16) + ((size_t)b << 10) + HID + jg];
        }

        float accf = 0.f, accn = 0.f;
        if (t > 0) {
            const float* hbase = out + (size_t)(t - 1) * BATCH * HID;

            // stage full 64x512 h tile: 16 LDG.128/thread at high MLP, then STS
            float4 r[16];
            #pragma unroll
            for (int i = 0; i < 16; i++) {
                const int f = tid + SCAN_THREADS * i;        // float4 index
                r[i] = *(const float4*)(hbase + (f >> 7) * HID + 4 * (f & 127));
            }
            #pragma unroll
            for (int i = 0; i < 16; i++) {
                const int f = tid + SCAN_THREADS * i;
                hsm[(f >> 7) * HSTRIDE + (f & 127)] = r[i];
            }
            __syncthreads();

            // packed dual-lane inner product over this thread's 256 k
            unsigned long long af0 = 0ull, af1 = 0ull, an0 = 0ull, an1 = 0ull;
            #pragma unroll
            for (int q = 0; q < 64; q++) {
                const ulonglong2 h2  = *(const ulonglong2*)&hb[q];
                const ulonglong2 wf2 = *(const ulonglong2*)&wfq[q];
                const ulonglong2 wn2 = *(const ulonglong2*)&wnq[q];
                fma2(af0, h2.x, wf2.x);
                fma2(an0, h2.x, wn2.x);
                fma2(af1, h2.y, wf2.y);
                fma2(an1, h2.y, wn2.y);
            }
            accf = hsum2(af0) + hsum2(af1);
            accn = hsum2(an0) + hsum2(an1);

            // cross-half reduction
            if (half == 1) hred[b * 4 + jl] = make_float2(accf, accn);
            __syncthreads();
            if (half == 0) {
                const float2 o = hred[b * 4 + jl];
                accf += o.x;
                accn += o.y;
            }
        }

        // gates + write h_t (half==0 threads own the 256 (b,j) outputs)
        if (half == 0) {
            const float f  = 1.f / (1.f + expf(-(gif + accf + bhf)));
            const float hv = tanhf(gin + f * (accn + bhn));
            out[((size_t)t * BATCH + b) * HID + jg] = hv;
        }
        gif = gif_n;
        gin = gin_n;
    }

    // self-reset barrier for next graph replay: last arriving CTA clears it.
    __syncthreads();
    if (tid == 0) {
        const unsigned r = atomicAdd(&g_bar, 1u);
        if (r == (unsigned)SCAN_CTAS * (unsigned)T_STEPS - 1u)
            *((volatile unsigned*)&g_bar) = 0u;
    }
}

extern "C" void kernel_launch(void* const* d_in, const int* in_sizes, int n_in,
                              void* d_out, int out_size) {
    const float* X   = (const float*)d_in[0];  // (512, 64, 512)
    const float* Wih = (const float*)d_in[1];  // (1024, 512)
    const float* Whh = (const float*)d_in[2];  // (1024, 512)
    const float* bih = (const float*)d_in[3];  // (1024,)
    const float* bhh = (const float*)d_in[4];  // (1024,)
    float* out = (float*)d_out;                // (512, 64, 512)

    cudaFuncSetAttribute(scan_kernel,
                         cudaFuncAttributeMaxDynamicSharedMemorySize, SMEM_BYTES);

    dim3 g1(GATES / 64, (T_STEPS * BATCH) / 64);
    gi_gemm<<<g1, 256>>>(X, Wih, bih);
    scan_kernel<<<SCAN_CTAS, SCAN_THREADS, SMEM_BYTES>>>(Whh, bhh, out);
}